// round 1
// baseline (speedup 1.0000x reference)
#include <cuda_runtime.h>
#include <math.h>

#define DD   1024
#define FF   2752
#define EE   8
#define NTOK 8192
#define NA   16384   /* NTOK * TOPK, exact */

// ---------------- scratch (static device globals; no allocation) ----------
__device__ int   g_counts[EE];
__device__ int   g_offsets[EE];
__device__ int   g_cursor[EE];
__device__ int   g_atok[NA];
__device__ int   g_aslot[NA];
__device__ float g_aw[NA];
__device__ int   g_tidx[NTOK * 2];
__device__ float g_tw[NTOK * 2];
__device__ float g_X13[(size_t)NA * 2 * FF];   // 16384 x 5504  (~360 MB)
__device__ float g_H[(size_t)NA * FF];         // 16384 x 2752  (~180 MB)
__device__ float g_OutK[2][(size_t)NTOK * DD]; // 2 x 8192 x 1024 (~64 MB)

// ---------------- small kernels -------------------------------------------
__global__ void init_kernel() {
    int t = threadIdx.x;
    if (t < EE) { g_counts[t] = 0; g_cursor[t] = 0; }
}

__global__ void router_kernel(const float* __restrict__ x,
                              const float* __restrict__ Wr) {
    int warp = (int)((blockIdx.x * blockDim.x + threadIdx.x) >> 5);
    int lane = threadIdx.x & 31;
    if (warp >= NTOK) return;
    const float* xr = x + (size_t)warp * DD;
    float acc[EE];
#pragma unroll
    for (int e = 0; e < EE; e++) acc[e] = 0.f;
    for (int d = lane; d < DD; d += 32) {
        float xv = xr[d];
        const float4* wp = (const float4*)(Wr + (size_t)d * EE);
        float4 w0 = wp[0], w1 = wp[1];
        acc[0] += xv * w0.x; acc[1] += xv * w0.y;
        acc[2] += xv * w0.z; acc[3] += xv * w0.w;
        acc[4] += xv * w1.x; acc[5] += xv * w1.y;
        acc[6] += xv * w1.z; acc[7] += xv * w1.w;
    }
#pragma unroll
    for (int e = 0; e < EE; e++) {
#pragma unroll
        for (int o = 16; o; o >>= 1)
            acc[e] += __shfl_xor_sync(0xffffffffu, acc[e], o);
    }
    if (lane == 0) {
        int i0 = 0;
#pragma unroll
        for (int e = 1; e < EE; e++) if (acc[e] > acc[i0]) i0 = e;
        int i1 = (i0 == 0) ? 1 : 0;
#pragma unroll
        for (int e = 0; e < EE; e++)
            if (e != i0 && acc[e] > acc[i1]) i1 = e;
        // top_probs renormalized == 2-way softmax of (l0, l1)
        float w0 = 1.f / (1.f + expf(acc[i1] - acc[i0]));
        float w1 = 1.f - w0;
        g_tidx[warp * 2 + 0] = i0; g_tidx[warp * 2 + 1] = i1;
        g_tw[warp * 2 + 0]   = w0; g_tw[warp * 2 + 1]   = w1;
        atomicAdd(&g_counts[i0], 1);
        atomicAdd(&g_counts[i1], 1);
    }
}

__global__ void scan_kernel() {
    if (threadIdx.x == 0) {
        int s = 0;
        for (int e = 0; e < EE; e++) { g_offsets[e] = s; s += g_counts[e]; }
    }
}

__global__ void build_kernel() {
    int n = blockIdx.x * blockDim.x + threadIdx.x;
    if (n >= NTOK) return;
#pragma unroll
    for (int k = 0; k < 2; k++) {
        int e = g_tidx[n * 2 + k];
        int p = atomicAdd(&g_cursor[e], 1);
        int a = g_offsets[e] + p;
        g_atok[a]  = n;
        g_aslot[a] = k;
        g_aw[a]    = g_tw[n * 2 + k];
    }
}

// ---------------- grouped SGEMM 1: X13[row] = x[tok(row)] @ W13[e] --------
// tiles 128x128x8, 8x8 microtile, 256 threads, double-buffered smem
__global__ void __launch_bounds__(256, 2)
gemm1_kernel(const float* __restrict__ x, const float* __restrict__ W13) {
    const int e     = blockIdx.z;
    const int cnt   = g_counts[e];
    const int mbase = blockIdx.y * 128;
    if (mbase >= cnt) return;
    const int off = g_offsets[e];
    const int n0  = blockIdx.x * 128;
    const int NB  = 2 * FF;
    const float* __restrict__ Bp = W13 + (size_t)e * DD * NB;

    __shared__ float As[2][8][128];
    __shared__ float Bs[2][8][128];

    const int tid = threadIdx.x;
    const int am  = tid >> 1;
    const int ak  = (tid & 1) * 4;
    const int arow = mbase + am;
    const int tok  = g_atok[off + (arow < cnt ? arow : 0)];
    const float* aptr = x + (size_t)tok * DD + ak;
    const int bk = tid >> 5;
    const int bn = (tid & 31) * 4;
    const float* bptr = Bp + (size_t)bk * NB + n0 + bn;

    const int tr = (tid >> 4) * 8;
    const int tc = (tid & 15) * 8;

    float acc[8][8];
#pragma unroll
    for (int i = 0; i < 8; i++)
#pragma unroll
        for (int j = 0; j < 8; j++) acc[i][j] = 0.f;

    float4 av = *(const float4*)(aptr);
    float4 bv = *(const float4*)(bptr);
    As[0][ak + 0][am] = av.x; As[0][ak + 1][am] = av.y;
    As[0][ak + 2][am] = av.z; As[0][ak + 3][am] = av.w;
    *(float4*)&Bs[0][bk][bn] = bv;
    __syncthreads();

    const int KT = DD / 8;
    int buf = 0;
    for (int kt = 0; kt < KT; kt++) {
        float4 an, bn4;
        if (kt + 1 < KT) {
            an  = *(const float4*)(aptr + (kt + 1) * 8);
            bn4 = *(const float4*)(bptr + (size_t)(kt + 1) * 8 * NB);
        }
#pragma unroll
        for (int kk = 0; kk < 8; kk++) {
            float a[8], b[8];
            *(float4*)(a)     = *(const float4*)&As[buf][kk][tr];
            *(float4*)(a + 4) = *(const float4*)&As[buf][kk][tr + 4];
            *(float4*)(b)     = *(const float4*)&Bs[buf][kk][tc];
            *(float4*)(b + 4) = *(const float4*)&Bs[buf][kk][tc + 4];
#pragma unroll
            for (int i = 0; i < 8; i++)
#pragma unroll
                for (int j = 0; j < 8; j++) acc[i][j] += a[i] * b[j];
        }
        if (kt + 1 < KT) {
            As[buf ^ 1][ak + 0][am] = an.x; As[buf ^ 1][ak + 1][am] = an.y;
            As[buf ^ 1][ak + 2][am] = an.z; As[buf ^ 1][ak + 3][am] = an.w;
            *(float4*)&Bs[buf ^ 1][bk][bn] = bn4;
            __syncthreads();
            buf ^= 1;
        }
    }
#pragma unroll
    for (int i = 0; i < 8; i++) {
        int m = mbase + tr + i;
        if (m < cnt) {
            float* cp = g_X13 + (size_t)(off + m) * NB + n0 + tc;
            *(float4*)(cp)     = make_float4(acc[i][0], acc[i][1], acc[i][2], acc[i][3]);
            *(float4*)(cp + 4) = make_float4(acc[i][4], acc[i][5], acc[i][6], acc[i][7]);
        }
    }
}

// ---------------- SwiGLU: H = silu(X13[:, :F]) * X13[:, F:] ---------------
__global__ void swiglu_kernel() {
    size_t idx = (size_t)blockIdx.x * blockDim.x + threadIdx.x;
    const size_t total = (size_t)NA * (FF / 4);
    if (idx >= total) return;
    size_t row = idx / (FF / 4);
    int j = (int)(idx % (FF / 4)) * 4;
    const float4 g = *(const float4*)&g_X13[row * (2 * FF) + j];
    const float4 u = *(const float4*)&g_X13[row * (2 * FF) + FF + j];
    float4 h;
    h.x = g.x / (1.f + expf(-g.x)) * u.x;
    h.y = g.y / (1.f + expf(-g.y)) * u.y;
    h.z = g.z / (1.f + expf(-g.z)) * u.z;
    h.w = g.w / (1.f + expf(-g.w)) * u.w;
    *(float4*)&g_H[row * FF + j] = h;
}

// ---------------- grouped SGEMM 2: OutK[slot][tok] = w * (H @ W2[e]) ------
__global__ void __launch_bounds__(256, 2)
gemm2_kernel(const float* __restrict__ W2) {
    const int e     = blockIdx.z;
    const int cnt   = g_counts[e];
    const int mbase = blockIdx.y * 128;
    if (mbase >= cnt) return;
    const int off = g_offsets[e];
    const int n0  = blockIdx.x * 128;
    const float* __restrict__ Bp = W2 + (size_t)e * FF * DD;

    __shared__ float As[2][8][128];
    __shared__ float Bs[2][8][128];

    const int tid = threadIdx.x;
    const int am  = tid >> 1;
    const int ak  = (tid & 1) * 4;
    int arow = mbase + am; if (arow >= cnt) arow = cnt - 1;
    const float* aptr = g_H + (size_t)(off + arow) * FF + ak;
    const int bk = tid >> 5;
    const int bn = (tid & 31) * 4;
    const float* bptr = Bp + (size_t)bk * DD + n0 + bn;

    const int tr = (tid >> 4) * 8;
    const int tc = (tid & 15) * 8;

    float acc[8][8];
#pragma unroll
    for (int i = 0; i < 8; i++)
#pragma unroll
        for (int j = 0; j < 8; j++) acc[i][j] = 0.f;

    float4 av = *(const float4*)(aptr);
    float4 bv = *(const float4*)(bptr);
    As[0][ak + 0][am] = av.x; As[0][ak + 1][am] = av.y;
    As[0][ak + 2][am] = av.z; As[0][ak + 3][am] = av.w;
    *(float4*)&Bs[0][bk][bn] = bv;
    __syncthreads();

    const int KT = FF / 8;   // 344
    int buf = 0;
    for (int kt = 0; kt < KT; kt++) {
        float4 an, bn4;
        if (kt + 1 < KT) {
            an  = *(const float4*)(aptr + (kt + 1) * 8);
            bn4 = *(const float4*)(bptr + (size_t)(kt + 1) * 8 * DD);
        }
#pragma unroll
        for (int kk = 0; kk < 8; kk++) {
            float a[8], b[8];
            *(float4*)(a)     = *(const float4*)&As[buf][kk][tr];
            *(float4*)(a + 4) = *(const float4*)&As[buf][kk][tr + 4];
            *(float4*)(b)     = *(const float4*)&Bs[buf][kk][tc];
            *(float4*)(b + 4) = *(const float4*)&Bs[buf][kk][tc + 4];
#pragma unroll
            for (int i = 0; i < 8; i++)
#pragma unroll
                for (int j = 0; j < 8; j++) acc[i][j] += a[i] * b[j];
        }
        if (kt + 1 < KT) {
            As[buf ^ 1][ak + 0][am] = an.x; As[buf ^ 1][ak + 1][am] = an.y;
            As[buf ^ 1][ak + 2][am] = an.z; As[buf ^ 1][ak + 3][am] = an.w;
            *(float4*)&Bs[buf ^ 1][bk][bn] = bn4;
            __syncthreads();
            buf ^= 1;
        }
    }
#pragma unroll
    for (int i = 0; i < 8; i++) {
        int m = mbase + tr + i;
        if (m < cnt) {
            int gi = off + m;
            int tokn = g_atok[gi];
            int slot = g_aslot[gi];
            float w  = g_aw[gi];
            float* cp = &g_OutK[slot][(size_t)tokn * DD + n0 + tc];
            *(float4*)(cp)     = make_float4(w * acc[i][0], w * acc[i][1], w * acc[i][2], w * acc[i][3]);
            *(float4*)(cp + 4) = make_float4(w * acc[i][4], w * acc[i][5], w * acc[i][6], w * acc[i][7]);
        }
    }
}

__global__ void finalize_kernel(float* __restrict__ out) {
    size_t idx = (size_t)blockIdx.x * blockDim.x + threadIdx.x;
    const size_t total = (size_t)NTOK * DD / 4;
    if (idx >= total) return;
    float4 a = ((const float4*)g_OutK[0])[idx];
    float4 b = ((const float4*)g_OutK[1])[idx];
    float4 r; r.x = a.x + b.x; r.y = a.y + b.y; r.z = a.z + b.z; r.w = a.w + b.w;
    ((float4*)out)[idx] = r;
}

// ---------------- launcher --------------------------------------------------
extern "C" void kernel_launch(void* const* d_in, const int* in_sizes, int n_in,
                              void* d_out, int out_size) {
    const float* x   = (const float*)d_in[0];  // [B,T,D]
    const float* W13 = (const float*)d_in[1];  // [E,D,2F]
    const float* W2  = (const float*)d_in[2];  // [E,F,D]
    const float* Wr  = (const float*)d_in[3];  // [D,E]
    float* out = (float*)d_out;

    init_kernel<<<1, 32>>>();
    router_kernel<<<NTOK / 8, 256>>>(x, Wr);        // 8 warps/block, warp/token
    scan_kernel<<<1, 32>>>();
    build_kernel<<<NTOK / 256, 256>>>();

    dim3 g1((2 * FF) / 128, NA / 128, EE);          // (43, 128, 8) w/ early exit
    gemm1_kernel<<<g1, 256>>>(x, W13);

    size_t sw_total = (size_t)NA * (FF / 4);
    swiglu_kernel<<<(unsigned)((sw_total + 255) / 256), 256>>>();

    dim3 g2(DD / 128, NA / 128, EE);                // (8, 128, 8) w/ early exit
    gemm2_kernel<<<g2, 256>>>(W2);

    finalize_kernel<<<(NTOK * DD / 4) / 256, 256>>>(out);
}

// round 3
// speedup vs baseline: 1.5645x; 1.5645x over previous
#include <cuda_runtime.h>
#include <cuda_bf16.h>
#include <math.h>
#include <stdint.h>

#define DD   1024
#define FF   2752
#define EE   8
#define NTOK 8192
#define NA   16384
#define NB13 (2*FF)   /* 5504 */

// ---------------- scratch (static device globals; no allocation) ----------
__device__ int   g_counts[EE];
__device__ int   g_offsets[EE];
__device__ int   g_cursor[EE];
__device__ int   g_atok[NA];
__device__ int   g_aslot[NA];
__device__ float g_aw[NA];
__device__ int   g_tidx[NTOK * 2];
__device__ float g_tw[NTOK * 2];

__device__ __nv_bfloat16 g_xh[(size_t)NTOK * DD];
__device__ __nv_bfloat16 g_xl[(size_t)NTOK * DD];
__device__ __nv_bfloat16 g_W13h[(size_t)EE * DD * NB13];
__device__ __nv_bfloat16 g_W13l[(size_t)EE * DD * NB13];
__device__ __nv_bfloat16 g_W2h[(size_t)EE * FF * DD];
__device__ __nv_bfloat16 g_W2l[(size_t)EE * FF * DD];
__device__ __nv_bfloat16 g_Hh[(size_t)NA * FF];
__device__ __nv_bfloat16 g_Hl[(size_t)NA * FF];
__device__ float g_X13[(size_t)NA * NB13];          // fp32, 360 MB
__device__ float g_OutK[2][(size_t)NTOK * DD];

// ---------------- small kernels -------------------------------------------
__global__ void init_kernel() {
    int t = threadIdx.x;
    if (t < EE) { g_counts[t] = 0; g_cursor[t] = 0; }
}

__device__ __forceinline__ void split_bf16(float v, __nv_bfloat16& h, __nv_bfloat16& l) {
    h = __float2bfloat16(v);
    l = __float2bfloat16(v - __bfloat162float(h));
}

// which: 0 = x, 1 = W13, 2 = W2
template <int WHICH>
__global__ void split_kernel(const float4* __restrict__ src, size_t n4) {
    size_t i = (size_t)blockIdx.x * blockDim.x + threadIdx.x;
    if (i >= n4) return;
    __nv_bfloat16* dh; __nv_bfloat16* dl;
    if (WHICH == 0)      { dh = g_xh;   dl = g_xl;   }
    else if (WHICH == 1) { dh = g_W13h; dl = g_W13l; }
    else                 { dh = g_W2h;  dl = g_W2l;  }
    float4 v = src[i];
    __nv_bfloat16 h0, l0, h1, l1, h2, l2, h3, l3;
    split_bf16(v.x, h0, l0); split_bf16(v.y, h1, l1);
    split_bf16(v.z, h2, l2); split_bf16(v.w, h3, l3);
    __nv_bfloat162 hp0 = {h0, h1}, hp1 = {h2, h3};
    __nv_bfloat162 lp0 = {l0, l1}, lp1 = {l2, l3};
    uint2 hw = { *(uint32_t*)&hp0, *(uint32_t*)&hp1 };
    uint2 lw = { *(uint32_t*)&lp0, *(uint32_t*)&lp1 };
    *(uint2*)(dh + i * 4) = hw;
    *(uint2*)(dl + i * 4) = lw;
}

__global__ void router_kernel(const float* __restrict__ x,
                              const float* __restrict__ Wr) {
    int warp = (int)((blockIdx.x * blockDim.x + threadIdx.x) >> 5);
    int lane = threadIdx.x & 31;
    if (warp >= NTOK) return;
    const float* xr = x + (size_t)warp * DD;
    float acc[EE];
#pragma unroll
    for (int e = 0; e < EE; e++) acc[e] = 0.f;
    for (int d = lane; d < DD; d += 32) {
        float xv = xr[d];
        const float4* wp = (const float4*)(Wr + (size_t)d * EE);
        float4 w0 = wp[0], w1 = wp[1];
        acc[0] += xv * w0.x; acc[1] += xv * w0.y;
        acc[2] += xv * w0.z; acc[3] += xv * w0.w;
        acc[4] += xv * w1.x; acc[5] += xv * w1.y;
        acc[6] += xv * w1.z; acc[7] += xv * w1.w;
    }
#pragma unroll
    for (int e = 0; e < EE; e++) {
#pragma unroll
        for (int o = 16; o; o >>= 1)
            acc[e] += __shfl_xor_sync(0xffffffffu, acc[e], o);
    }
    if (lane == 0) {
        int i0 = 0;
#pragma unroll
        for (int e = 1; e < EE; e++) if (acc[e] > acc[i0]) i0 = e;
        int i1 = (i0 == 0) ? 1 : 0;
#pragma unroll
        for (int e = 0; e < EE; e++)
            if (e != i0 && acc[e] > acc[i1]) i1 = e;
        float w0 = 1.f / (1.f + expf(acc[i1] - acc[i0]));
        float w1 = 1.f - w0;
        g_tidx[warp * 2 + 0] = i0; g_tidx[warp * 2 + 1] = i1;
        g_tw[warp * 2 + 0]   = w0; g_tw[warp * 2 + 1]   = w1;
        atomicAdd(&g_counts[i0], 1);
        atomicAdd(&g_counts[i1], 1);
    }
}

__global__ void scan_kernel() {
    if (threadIdx.x == 0) {
        int s = 0;
        for (int e = 0; e < EE; e++) { g_offsets[e] = s; s += g_counts[e]; }
    }
}

__global__ void build_kernel() {
    int n = blockIdx.x * blockDim.x + threadIdx.x;
    if (n >= NTOK) return;
#pragma unroll
    for (int k = 0; k < 2; k++) {
        int e = g_tidx[n * 2 + k];
        int p = atomicAdd(&g_cursor[e], 1);
        int a = g_offsets[e] + p;
        g_atok[a]  = n;
        g_aslot[a] = k;
        g_aw[a]    = g_tw[n * 2 + k];
    }
}

// ---------------- split-bf16 tensor-core grouped GEMM ---------------------
// CTA tile 128x128, K-chunk 16, 8 warps (2x4) of 64x32, mma.m16n8k16 bf16.
// acc += Ah*Bh + Ah*Bl + Al*Bh  (3 HMMAs per fragment set).
// blockIdx.x = m-tile (fastest -> weight L2 reuse), y = n-tile, z = expert.

#define HMMA(d, a0, a1, a2, a3, b0, b1)                                        \
    asm volatile(                                                              \
        "mma.sync.aligned.m16n8k16.row.col.f32.bf16.bf16.f32 "                 \
        "{%0,%1,%2,%3}, {%4,%5,%6,%7}, {%8,%9}, {%0,%1,%2,%3};\n"              \
        : "+f"(d[0]), "+f"(d[1]), "+f"(d[2]), "+f"(d[3])                       \
        : "r"(a0), "r"(a1), "r"(a2), "r"(a3), "r"(b0), "r"(b1))

template <bool G1>
__global__ void __launch_bounds__(256, 2)
hgemm_kernel() {
    const int e     = blockIdx.z;
    const int cnt   = g_counts[e];
    const int mbase = blockIdx.x * 128;
    if (mbase >= cnt) return;
    const int off = g_offsets[e];
    const int n0  = blockIdx.y * 128;
    const int KDIM = G1 ? DD : FF;
    const int LDB  = G1 ? NB13 : DD;

    const __nv_bfloat16* __restrict__ BH = (G1 ? g_W13h : g_W2h) + (size_t)e * KDIM * LDB;
    const __nv_bfloat16* __restrict__ BL = (G1 ? g_W13l : g_W2l) + (size_t)e * KDIM * LDB;

    // [buf][comp][m][k2], k2 = k/2 packed bf16x2 words; row padded to 12 words
    __shared__ uint32_t AsU[2][2][128][12];
    // [buf][comp][k2][n]: word = {B[2k2][n], B[2k2+1][n]}
    __shared__ uint32_t BsU[2][2][8][128];

    const int tid  = threadIdx.x;
    const int warp = tid >> 5, lane = tid & 31;
    const int grp  = lane >> 2, tig = lane & 3;
    const int wm   = (warp >> 2) * 64, wn = (warp & 3) * 32;

    // loaders: comp = tid>>7
    const int l_comp = tid >> 7;
    const int l_row  = tid & 127;
    int arow_g = mbase + l_row; if (arow_g >= cnt) arow_g = cnt - 1;
    const __nv_bfloat16* aptr;
    if (G1) aptr = (l_comp ? g_xl : g_xh) + (size_t)g_atok[off + arow_g] * DD;
    else    aptr = (l_comp ? g_Hl : g_Hh) + (size_t)(off + arow_g) * FF;

    const int b_k2 = (tid >> 4) & 7;
    const int b_ns = (tid & 15) * 8;
    const __nv_bfloat16* bptr = (l_comp ? BL : BH) + (size_t)(2 * b_k2) * LDB + n0 + b_ns;

    float acc[4][4][4];
#pragma unroll
    for (int a = 0; a < 4; a++)
#pragma unroll
        for (int b = 0; b < 4; b++)
#pragma unroll
            for (int c = 0; c < 4; c++) acc[a][b][c] = 0.f;

    const int KT = KDIM / 16;

    uint4 aR0 = *(const uint4*)(aptr);       // bf16 k 0..7
    uint4 aR1 = *(const uint4*)(aptr + 8);   // bf16 k 8..15
    uint4 bR0 = *(const uint4*)(bptr);           // row 2k2, n..n+7
    uint4 bR1 = *(const uint4*)(bptr + LDB);     // row 2k2+1

    // store chunk 0 into buf 0
    {
        *(uint4*)&AsU[0][l_comp][l_row][0] = aR0;
        *(uint4*)&AsU[0][l_comp][l_row][4] = aR1;
        uint32_t o[8];
        o[0] = __byte_perm(bR0.x, bR1.x, 0x5410); o[1] = __byte_perm(bR0.x, bR1.x, 0x7632);
        o[2] = __byte_perm(bR0.y, bR1.y, 0x5410); o[3] = __byte_perm(bR0.y, bR1.y, 0x7632);
        o[4] = __byte_perm(bR0.z, bR1.z, 0x5410); o[5] = __byte_perm(bR0.z, bR1.z, 0x7632);
        o[6] = __byte_perm(bR0.w, bR1.w, 0x5410); o[7] = __byte_perm(bR0.w, bR1.w, 0x7632);
        *(uint4*)&BsU[0][l_comp][b_k2][b_ns]     = make_uint4(o[0], o[1], o[2], o[3]);
        *(uint4*)&BsU[0][l_comp][b_k2][b_ns + 4] = make_uint4(o[4], o[5], o[6], o[7]);
    }
    __syncthreads();

    int buf = 0;
    for (int kt = 0; kt < KT; kt++) {
        if (kt + 1 < KT) {
            const __nv_bfloat16* ap = aptr + (kt + 1) * 16;
            const __nv_bfloat16* bp = bptr + (size_t)(kt + 1) * 16 * LDB;
            aR0 = *(const uint4*)(ap);
            aR1 = *(const uint4*)(ap + 8);
            bR0 = *(const uint4*)(bp);
            bR1 = *(const uint4*)(bp + LDB);
        }

        // B fragments (hi & lo)
        uint32_t bh[4][2], bl[4][2];
#pragma unroll
        for (int nf = 0; nf < 4; nf++) {
            const int c = wn + nf * 8 + grp;
            bh[nf][0] = BsU[buf][0][tig][c];
            bh[nf][1] = BsU[buf][0][tig + 4][c];
            bl[nf][0] = BsU[buf][1][tig][c];
            bl[nf][1] = BsU[buf][1][tig + 4][c];
        }
        // A-hi fragments, then Ah*Bh and Ah*Bl
        {
            uint32_t af[4][4];
#pragma unroll
            for (int mf = 0; mf < 4; mf++) {
                const int r = wm + mf * 16 + grp;
                af[mf][0] = AsU[buf][0][r][tig];
                af[mf][1] = AsU[buf][0][r + 8][tig];
                af[mf][2] = AsU[buf][0][r][tig + 4];
                af[mf][3] = AsU[buf][0][r + 8][tig + 4];
            }
#pragma unroll
            for (int mf = 0; mf < 4; mf++)
#pragma unroll
                for (int nf = 0; nf < 4; nf++) {
                    HMMA(acc[mf][nf], af[mf][0], af[mf][1], af[mf][2], af[mf][3],
                         bh[nf][0], bh[nf][1]);
                    HMMA(acc[mf][nf], af[mf][0], af[mf][1], af[mf][2], af[mf][3],
                         bl[nf][0], bl[nf][1]);
                }
        }
        // A-lo fragments, Al*Bh
        {
            uint32_t af[4][4];
#pragma unroll
            for (int mf = 0; mf < 4; mf++) {
                const int r = wm + mf * 16 + grp;
                af[mf][0] = AsU[buf][1][r][tig];
                af[mf][1] = AsU[buf][1][r + 8][tig];
                af[mf][2] = AsU[buf][1][r][tig + 4];
                af[mf][3] = AsU[buf][1][r + 8][tig + 4];
            }
#pragma unroll
            for (int mf = 0; mf < 4; mf++)
#pragma unroll
                for (int nf = 0; nf < 4; nf++)
                    HMMA(acc[mf][nf], af[mf][0], af[mf][1], af[mf][2], af[mf][3],
                         bh[nf][0], bh[nf][1]);
        }

        if (kt + 1 < KT) {
            *(uint4*)&AsU[buf ^ 1][l_comp][l_row][0] = aR0;
            *(uint4*)&AsU[buf ^ 1][l_comp][l_row][4] = aR1;
            uint32_t o[8];
            o[0] = __byte_perm(bR0.x, bR1.x, 0x5410); o[1] = __byte_perm(bR0.x, bR1.x, 0x7632);
            o[2] = __byte_perm(bR0.y, bR1.y, 0x5410); o[3] = __byte_perm(bR0.y, bR1.y, 0x7632);
            o[4] = __byte_perm(bR0.z, bR1.z, 0x5410); o[5] = __byte_perm(bR0.z, bR1.z, 0x7632);
            o[6] = __byte_perm(bR0.w, bR1.w, 0x5410); o[7] = __byte_perm(bR0.w, bR1.w, 0x7632);
            *(uint4*)&BsU[buf ^ 1][l_comp][b_k2][b_ns]     = make_uint4(o[0], o[1], o[2], o[3]);
            *(uint4*)&BsU[buf ^ 1][l_comp][b_k2][b_ns + 4] = make_uint4(o[4], o[5], o[6], o[7]);
            __syncthreads();
            buf ^= 1;
        }
    }

    // epilogue (C frag: c0,c1 @ row grp cols 2tig,2tig+1; c2,c3 @ row grp+8)
#pragma unroll
    for (int mf = 0; mf < 4; mf++) {
#pragma unroll
        for (int i = 0; i < 2; i++) {
            const int m = mbase + wm + mf * 16 + grp + i * 8;
            if (m < cnt) {
                const int gi = off + m;
                if (G1) {
                    float* cp = g_X13 + (size_t)gi * NB13 + n0 + wn + 2 * tig;
#pragma unroll
                    for (int nf = 0; nf < 4; nf++)
                        *(float2*)(cp + nf * 8) =
                            make_float2(acc[mf][nf][2 * i], acc[mf][nf][2 * i + 1]);
                } else {
                    const int   tokn = g_atok[gi];
                    const int   slot = g_aslot[gi];
                    const float w    = g_aw[gi];
                    float* cp = &g_OutK[slot][(size_t)tokn * DD + n0 + wn + 2 * tig];
#pragma unroll
                    for (int nf = 0; nf < 4; nf++)
                        *(float2*)(cp + nf * 8) =
                            make_float2(w * acc[mf][nf][2 * i], w * acc[mf][nf][2 * i + 1]);
                }
            }
        }
    }
}

// ---------------- SwiGLU: H(split bf16) = silu(X13[:, :F]) * X13[:, F:] ----
__global__ void swiglu_kernel() {
    size_t idx = (size_t)blockIdx.x * blockDim.x + threadIdx.x;
    const size_t total = (size_t)NA * (FF / 4);
    if (idx >= total) return;
    size_t row = idx / (FF / 4);
    int j = (int)(idx % (FF / 4)) * 4;
    const float4 g = *(const float4*)&g_X13[row * NB13 + j];
    const float4 u = *(const float4*)&g_X13[row * NB13 + FF + j];
    float4 h;
    h.x = g.x / (1.f + expf(-g.x)) * u.x;
    h.y = g.y / (1.f + expf(-g.y)) * u.y;
    h.z = g.z / (1.f + expf(-g.z)) * u.z;
    h.w = g.w / (1.f + expf(-g.w)) * u.w;
    __nv_bfloat16 h0, l0, h1, l1, h2, l2, h3, l3;
    split_bf16(h.x, h0, l0); split_bf16(h.y, h1, l1);
    split_bf16(h.z, h2, l2); split_bf16(h.w, h3, l3);
    __nv_bfloat162 hp0 = {h0, h1}, hp1 = {h2, h3};
    __nv_bfloat162 lp0 = {l0, l1}, lp1 = {l2, l3};
    *(uint2*)&g_Hh[row * FF + j] = make_uint2(*(uint32_t*)&hp0, *(uint32_t*)&hp1);
    *(uint2*)&g_Hl[row * FF + j] = make_uint2(*(uint32_t*)&lp0, *(uint32_t*)&lp1);
}

__global__ void finalize_kernel(float* __restrict__ out) {
    size_t idx = (size_t)blockIdx.x * blockDim.x + threadIdx.x;
    const size_t total = (size_t)NTOK * DD / 4;
    if (idx >= total) return;
    float4 a = ((const float4*)g_OutK[0])[idx];
    float4 b = ((const float4*)g_OutK[1])[idx];
    float4 r; r.x = a.x + b.x; r.y = a.y + b.y; r.z = a.z + b.z; r.w = a.w + b.w;
    ((float4*)out)[idx] = r;
}

// ---------------- launcher --------------------------------------------------
extern "C" void kernel_launch(void* const* d_in, const int* in_sizes, int n_in,
                              void* d_out, int out_size) {
    const float* x   = (const float*)d_in[0];  // [B,T,D]
    const float* W13 = (const float*)d_in[1];  // [E,D,2F]
    const float* W2  = (const float*)d_in[2];  // [E,F,D]
    const float* Wr  = (const float*)d_in[3];  // [D,E]
    float* out = (float*)d_out;

    init_kernel<<<1, 32>>>();
    router_kernel<<<NTOK / 8, 256>>>(x, Wr);
    scan_kernel<<<1, 32>>>();
    build_kernel<<<NTOK / 256, 256>>>();

    {
        size_t n4 = (size_t)NTOK * DD / 4;
        split_kernel<0><<<(unsigned)((n4 + 255) / 256), 256>>>((const float4*)x, n4);
    }
    {
        size_t n4 = (size_t)EE * DD * NB13 / 4;
        split_kernel<1><<<(unsigned)((n4 + 255) / 256), 256>>>((const float4*)W13, n4);
    }
    {
        size_t n4 = (size_t)EE * FF * DD / 4;
        split_kernel<2><<<(unsigned)((n4 + 255) / 256), 256>>>((const float4*)W2, n4);
    }

    dim3 g1(NA / 128, NB13 / 128, EE);   // (128, 43, 8), m-fastest
    hgemm_kernel<true><<<g1, 256>>>();

    size_t sw_total = (size_t)NA * (FF / 4);
    swiglu_kernel<<<(unsigned)((sw_total + 255) / 256), 256>>>();

    dim3 g2(NA / 128, DD / 128, EE);     // (128, 8, 8)
    hgemm_kernel<false><<<g2, 256>>>();

    finalize_kernel<<<(NTOK * DD / 4) / 256, 256>>>(out);
}

// round 5
// speedup vs baseline: 3.9145x; 2.5021x over previous
#include <cuda_runtime.h>
#include <cuda_fp16.h>
#include <math.h>
#include <stdint.h>

#define DD   1024
#define FF   2752
#define EE   8
#define NTOK 8192
#define NA   16384
#define NB13 (2*FF)   /* 5504 */

// ---------------- scratch (static device globals; no allocation) ----------
__device__ int   g_counts[EE];
__device__ int   g_offsets[EE];
__device__ int   g_cursor[EE];
__device__ int   g_atok[NA];
__device__ int   g_aslot[NA];
__device__ float g_aw[NA];
__device__ int   g_tidx[NTOK * 2];
__device__ float g_tw[NTOK * 2];

__device__ __half g_xf[(size_t)NTOK * DD];            // fp16 x
__device__ __half g_W13f[(size_t)EE * NB13 * DD];     // K-major [E][N][K]
__device__ __half g_W2f[(size_t)EE * DD * FF];        // K-major [E][N][K]
__device__ __half g_Hf[(size_t)NA * FF];              // fp16 H
__device__ float  g_OutK[2][(size_t)NTOK * DD];

// ---------------- helpers ---------------------------------------------------
__device__ __forceinline__ uint32_t smem_u32(const void* p) {
    uint32_t a;
    asm("{ .reg .u64 t; cvta.to.shared.u64 t, %1; cvt.u32.u64 %0, t; }"
        : "=r"(a) : "l"(p));
    return a;
}
#define CPA16(dst, src) \
    asm volatile("cp.async.cg.shared.global [%0], [%1], 16;\n" :: "r"(dst), "l"(src) : "memory")
#define CPA_COMMIT()  asm volatile("cp.async.commit_group;\n" ::: "memory")
#define CPA_WAIT1()   asm volatile("cp.async.wait_group 1;\n" ::: "memory")

#define HMMA(d, a0, a1, a2, a3, b0, b1)                                        \
    asm volatile(                                                              \
        "mma.sync.aligned.m16n8k16.row.col.f32.f16.f16.f32 "                   \
        "{%0,%1,%2,%3}, {%4,%5,%6,%7}, {%8,%9}, {%0,%1,%2,%3};\n"              \
        : "+f"((d)[0]), "+f"((d)[1]), "+f"((d)[2]), "+f"((d)[3])               \
        : "r"(a0), "r"(a1), "r"(a2), "r"(a3), "r"(b0), "r"(b1))

// ---------------- small kernels -------------------------------------------
__global__ void init_kernel() {
    int t = threadIdx.x;
    if (t < EE) { g_counts[t] = 0; g_cursor[t] = 0; }
}

__global__ void xconv_kernel(const float4* __restrict__ src, size_t n4) {
    size_t i = (size_t)blockIdx.x * blockDim.x + threadIdx.x;
    if (i >= n4) return;
    float4 v = src[i];
    __half2 p0 = __floats2half2_rn(v.x, v.y);
    __half2 p1 = __floats2half2_rn(v.z, v.w);
    *(uint2*)(g_xf + i * 4) = make_uint2(*(uint32_t*)&p0, *(uint32_t*)&p1);
}

// transpose: src fp32 [E][KSRC][NSRC] -> dst fp16 K-major [E][NSRC][KSRC]
template <int KSRC, int NSRC, int W13SEL>
__global__ void trans_f16_kernel(const float* __restrict__ src) {
    __shared__ float tile[64][33];
    const int e  = blockIdx.z;
    const int n0 = blockIdx.x * 32;
    const int k0 = blockIdx.y * 64;
    const int tx = threadIdx.x, ty = threadIdx.y;  // (32, 8)
    const float* s = src + (size_t)e * KSRC * NSRC;
#pragma unroll
    for (int i = 0; i < 8; i++) {
        int k = ty + i * 8;
        tile[k][tx] = s[(size_t)(k0 + k) * NSRC + n0 + tx];
    }
    __syncthreads();
    __half* d = (W13SEL ? g_W13f : g_W2f) + (size_t)e * NSRC * KSRC;
#pragma unroll
    for (int i = 0; i < 4; i++) {
        int ny = ty + i * 8;
        __half2 p = __floats2half2_rn(tile[2 * tx][ny], tile[2 * tx + 1][ny]);
        *(__half2*)(d + (size_t)(n0 + ny) * KSRC + k0 + 2 * tx) = p;
    }
}

__global__ void router_kernel(const float* __restrict__ x,
                              const float* __restrict__ Wr) {
    int warp = (int)((blockIdx.x * blockDim.x + threadIdx.x) >> 5);
    int lane = threadIdx.x & 31;
    if (warp >= NTOK) return;
    const float* xr = x + (size_t)warp * DD;
    float acc[EE];
#pragma unroll
    for (int e = 0; e < EE; e++) acc[e] = 0.f;
    for (int d = lane; d < DD; d += 32) {
        float xv = xr[d];
        const float4* wp = (const float4*)(Wr + (size_t)d * EE);
        float4 w0 = wp[0], w1 = wp[1];
        acc[0] += xv * w0.x; acc[1] += xv * w0.y;
        acc[2] += xv * w0.z; acc[3] += xv * w0.w;
        acc[4] += xv * w1.x; acc[5] += xv * w1.y;
        acc[6] += xv * w1.z; acc[7] += xv * w1.w;
    }
#pragma unroll
    for (int e = 0; e < EE; e++) {
#pragma unroll
        for (int o = 16; o; o >>= 1)
            acc[e] += __shfl_xor_sync(0xffffffffu, acc[e], o);
    }
    if (lane == 0) {
        int i0 = 0;
#pragma unroll
        for (int e = 1; e < EE; e++) if (acc[e] > acc[i0]) i0 = e;
        int i1 = (i0 == 0) ? 1 : 0;
#pragma unroll
        for (int e = 0; e < EE; e++)
            if (e != i0 && acc[e] > acc[i1]) i1 = e;
        float w0 = 1.f / (1.f + expf(acc[i1] - acc[i0]));
        float w1 = 1.f - w0;
        g_tidx[warp * 2 + 0] = i0; g_tidx[warp * 2 + 1] = i1;
        g_tw[warp * 2 + 0]   = w0; g_tw[warp * 2 + 1]   = w1;
        atomicAdd(&g_counts[i0], 1);
        atomicAdd(&g_counts[i1], 1);
    }
}

__global__ void scan_kernel() {
    if (threadIdx.x == 0) {
        int s = 0;
        for (int e = 0; e < EE; e++) { g_offsets[e] = s; s += g_counts[e]; }
    }
}

__global__ void build_kernel() {
    int n = blockIdx.x * blockDim.x + threadIdx.x;
    if (n >= NTOK) return;
#pragma unroll
    for (int k = 0; k < 2; k++) {
        int e = g_tidx[n * 2 + k];
        int p = atomicAdd(&g_cursor[e], 1);
        int a = g_offsets[e] + p;
        g_atok[a]  = n;
        g_aslot[a] = k;
        g_aw[a]    = g_tw[n * 2 + k];
    }
}

// ---------------- fp16 tensor-core grouped GEMM ----------------------------
// CTA: M=128.  G1: N = 64 gate + 64 up (fused SwiGLU epilogue -> fp16 H).
//              G2: N = 128 output cols (scaled scatter to OutK).
// 8 warps = 4(m:32) x 2(n:32); each warp holds 2 accumulator sets:
//   G1: set0 = gate[n32], set1 = up[same n32]   (B rows 0-63 gate, 64-127 up)
//   G2: set0 = cols n32,  set1 = cols n32+64    (B rows = 128 out cols)
// smem per stage: A[128 rows][80B] + B[128 rows][80B] = 20480B; 3 stages.
// rows hold 32 fp16 of K (64B data + 16B pad -> conflict-free LDS).

#define STAGE_B   20480u
#define STAGE_W   5120
#define SMEM_GEMM (3 * 20480)

template <bool G1>
__global__ void __launch_bounds__(256, 2)
hgemm_tc_kernel() {
    constexpr int KDIM = G1 ? DD : FF;
    constexpr int KT   = KDIM / 32;

    const int e     = blockIdx.z;
    const int cnt   = g_counts[e];
    const int mbase = blockIdx.x * 128;
    if (mbase >= cnt) return;
    const int off = g_offsets[e];
    const int nb  = blockIdx.y;

    extern __shared__ __align__(16) uint32_t smw[];
    const uint32_t sb = smem_u32(smw);

    const int tid  = threadIdx.x;
    const int warp = tid >> 5, lane = tid & 31;
    const int grp  = lane >> 2, tig = lane & 3;
    const int mrow0 = (warp >> 1) * 32;
    const int ncol0 = (warp & 1) * 32;

    // ---- fill setup: thread -> (row, half); 2 x 16B for A, 2 x 16B for B ----
    const int fr = tid & 127, fh = tid >> 7;
    const __half* aP;
    {
        int rg = mbase + fr; if (rg >= cnt) rg = cnt - 1;
        if (G1) aP = g_xf + (size_t)g_atok[off + rg] * DD + fh * 16;
        else    aP = g_Hf + (size_t)(off + rg) * FF + fh * 16;
    }
    const __half* bP;
    {
        if (G1) {
            int n = (fr < 64) ? (nb * 64 + fr) : (FF + nb * 64 + (fr - 64));
            bP = g_W13f + ((size_t)e * NB13 + n) * DD + fh * 16;
        } else {
            int n = nb * 128 + fr;
            bP = g_W2f + ((size_t)e * DD + n) * FF + fh * 16;
        }
    }
    const uint32_t offA = (uint32_t)fr * 80u + (uint32_t)fh * 32u;
    const uint32_t offB = 10240u + offA;

#define FILL(st, kt) do {                                                      \
    uint32_t _a = sb + (uint32_t)(st) * STAGE_B + offA;                        \
    uint32_t _b = sb + (uint32_t)(st) * STAGE_B + offB;                        \
    const __half* _as = aP + (kt) * 32;                                        \
    const __half* _bs = bP + (kt) * 32;                                        \
    CPA16(_a,      _as);                                                       \
    CPA16(_a + 16, _as + 8);                                                   \
    CPA16(_b,      _bs);                                                       \
    CPA16(_b + 16, _bs + 8);                                                   \
} while (0)

    float acc[2][2][4][4];
#pragma unroll
    for (int s = 0; s < 2; s++)
#pragma unroll
        for (int a = 0; a < 2; a++)
#pragma unroll
            for (int b = 0; b < 4; b++)
#pragma unroll
                for (int c = 0; c < 4; c++) acc[s][a][b][c] = 0.f;

    // prologue: stages 0,1
    FILL(0, 0); CPA_COMMIT();
    FILL(1, 1); CPA_COMMIT();

    int st = 0;
    for (int kt = 0; kt < KT; kt++) {
        CPA_WAIT1();
        __syncthreads();
        {   // fill stage (kt+2)%3 == previous stage slot, safe after barrier
            int sf = st + 2; if (sf >= 3) sf -= 3;
            if (kt + 2 < KT) FILL(sf, kt + 2);
            CPA_COMMIT();
        }
        const int wA = st * STAGE_W;
        const int wB = st * STAGE_W + 2560;
#pragma unroll
        for (int ks = 0; ks < 2; ks++) {
            uint32_t af[2][4];
#pragma unroll
            for (int mf = 0; mf < 2; mf++) {
                const int r = mrow0 + mf * 16 + grp;
                const int kw = ks * 8 + tig;
                af[mf][0] = smw[wA + r * 20 + kw];
                af[mf][1] = smw[wA + (r + 8) * 20 + kw];
                af[mf][2] = smw[wA + r * 20 + kw + 4];
                af[mf][3] = smw[wA + (r + 8) * 20 + kw + 4];
            }
#pragma unroll
            for (int s = 0; s < 2; s++)
#pragma unroll
                for (int nf = 0; nf < 4; nf++) {
                    const int n = s * 64 + ncol0 + nf * 8 + grp;
                    const int kw = ks * 8 + tig;
                    uint32_t b0 = smw[wB + n * 20 + kw];
                    uint32_t b1 = smw[wB + n * 20 + kw + 4];
                    HMMA(acc[s][0][nf], af[0][0], af[0][1], af[0][2], af[0][3], b0, b1);
                    HMMA(acc[s][1][nf], af[1][0], af[1][1], af[1][2], af[1][3], b0, b1);
                }
        }
        if (++st == 3) st = 0;
    }

    // ---- epilogue (accumulators in registers) ----
#pragma unroll
    for (int mf = 0; mf < 2; mf++) {
#pragma unroll
        for (int i = 0; i < 2; i++) {
            const int m = mbase + mrow0 + mf * 16 + grp + i * 8;
            if (m >= cnt) continue;
            const size_t gi = (size_t)off + m;
            if (G1) {
                __half* dp = g_Hf + gi * FF + nb * 64 + ncol0 + 2 * tig;
#pragma unroll
                for (int nf = 0; nf < 4; nf++) {
                    float g0 = acc[0][mf][nf][2 * i];
                    float g1 = acc[0][mf][nf][2 * i + 1];
                    float u0 = acc[1][mf][nf][2 * i];
                    float u1 = acc[1][mf][nf][2 * i + 1];
                    float v0 = g0 / (1.f + expf(-g0)) * u0;
                    float v1 = g1 / (1.f + expf(-g1)) * u1;
                    *(__half2*)(dp + nf * 8) = __floats2half2_rn(v0, v1);
                }
            } else {
                const int   tokn = g_atok[gi];
                const int   slot = g_aslot[gi];
                const float w    = g_aw[gi];
                float* cp = &g_OutK[slot][(size_t)tokn * DD + nb * 128 + ncol0 + 2 * tig];
#pragma unroll
                for (int s = 0; s < 2; s++)
#pragma unroll
                    for (int nf = 0; nf < 4; nf++)
                        *(float2*)(cp + s * 64 + nf * 8) = make_float2(
                            w * acc[s][mf][nf][2 * i], w * acc[s][mf][nf][2 * i + 1]);
            }
        }
    }
#undef FILL
}

__global__ void finalize_kernel(float* __restrict__ out) {
    size_t idx = (size_t)blockIdx.x * blockDim.x + threadIdx.x;
    const size_t total = (size_t)NTOK * DD / 4;
    if (idx >= total) return;
    float4 a = ((const float4*)g_OutK[0])[idx];
    float4 b = ((const float4*)g_OutK[1])[idx];
    float4 r; r.x = a.x + b.x; r.y = a.y + b.y; r.z = a.z + b.z; r.w = a.w + b.w;
    ((float4*)out)[idx] = r;
}

// ---------------- launcher --------------------------------------------------
extern "C" void kernel_launch(void* const* d_in, const int* in_sizes, int n_in,
                              void* d_out, int out_size) {
    const float* x   = (const float*)d_in[0];  // [B,T,D]
    const float* W13 = (const float*)d_in[1];  // [E,D,2F]
    const float* W2  = (const float*)d_in[2];  // [E,F,D]
    const float* Wr  = (const float*)d_in[3];  // [D,E]
    float* out = (float*)d_out;

    init_kernel<<<1, 32>>>();
    router_kernel<<<NTOK / 8, 256>>>(x, Wr);
    scan_kernel<<<1, 32>>>();
    build_kernel<<<NTOK / 256, 256>>>();

    {
        size_t n4 = (size_t)NTOK * DD / 4;
        xconv_kernel<<<(unsigned)((n4 + 255) / 256), 256>>>((const float4*)x, n4);
    }
    {   // W13: [E][1024][5504] -> K-major [E][5504][1024]
        dim3 g(NB13 / 32, DD / 64, EE);
        trans_f16_kernel<DD, NB13, 1><<<g, dim3(32, 8)>>>(W13);
    }
    {   // W2: [E][2752][1024] -> K-major [E][1024][2752]
        dim3 g(DD / 32, FF / 64, EE);
        trans_f16_kernel<FF, DD, 0><<<g, dim3(32, 8)>>>(W2);
    }

    cudaFuncSetAttribute(hgemm_tc_kernel<true>,
                         cudaFuncAttributeMaxDynamicSharedMemorySize, SMEM_GEMM);
    cudaFuncSetAttribute(hgemm_tc_kernel<false>,
                         cudaFuncAttributeMaxDynamicSharedMemorySize, SMEM_GEMM);

    dim3 g1(NA / 128, FF / 64, EE);     // (128, 43, 8) m-fastest
    hgemm_tc_kernel<true><<<g1, 256, SMEM_GEMM>>>();

    dim3 g2(NA / 128, DD / 128, EE);    // (128, 8, 8)
    hgemm_tc_kernel<false><<<g2, 256, SMEM_GEMM>>>();

    finalize_kernel<<<(NTOK * DD / 4) / 256, 256>>>(out);
}